// round 15
// baseline (speedup 1.0000x reference)
#include <cuda_runtime.h>

#define NATOMS 100000
#define NPAIRS 2000000
#define FDIM 64
#define RDIM 16
#define LN2F 0.6931471805599453f

typedef unsigned long long u64;

// Scratch (device globals: allocation-free per harness rules)
__device__ float g_yj[NATOMS * FDIM];   // softplus(x@Wj+bj) per atom
__device__ float g_acc[NATOMS * FDIM];  // x_i' -> (gather) -> v
__device__ int   g_cnt[NATOMS];         // pairs per destination atom
__device__ int   g_off[NATOMS];         // CSR offsets
__device__ int   g_cur[NATOMS];         // scatter cursors
__device__ int   g_part[98];            // scan partials (98*1024 >= NATOMS)
__device__ int   g_poff[98];            // scanned partials
__device__ int   g_plist[NPAIRS];       // pair ids bucketed by idx_i

__device__ __forceinline__ float sp(float x) {
    return fmaxf(x, 0.f) + log1pf(__expf(-fabsf(x)));
}

// ---- packed f32x2 helpers ----
__device__ __forceinline__ u64 fma2(u64 a, u64 b, u64 c) {
    u64 d;
    asm("fma.rn.f32x2 %0, %1, %2, %3;" : "=l"(d) : "l"(a), "l"(b), "l"(c));
    return d;
}
__device__ __forceinline__ u64 add2(u64 a, u64 b) {
    u64 d;
    asm("add.rn.f32x2 %0, %1, %2;" : "=l"(d) : "l"(a), "l"(b));
    return d;
}
__device__ __forceinline__ u64 splat2(float v) {
    u64 r;
    asm("mov.b64 %0, {%1, %1};" : "=l"(r) : "f"(v));
    return r;
}
__device__ __forceinline__ u64 pack2(float lo, float hi) {
    u64 r;
    asm("mov.b64 %0, {%1, %2};" : "=l"(r) : "f"(lo), "f"(hi));
    return r;
}
__device__ __forceinline__ float2 unpack2(u64 v) {
    float lo, hi;
    asm("mov.b64 {%0, %1}, %2;" : "=f"(lo), "=f"(hi) : "l"(v));
    return make_float2(lo, hi);
}

// ---------------------------------------------------------------------------
// Kernel 1: node transforms (unchanged from R11). x = sp(emb)-ln2;
// g_acc = sp(x@Wi+bi); g_yj = sp(x@Wj+bj). One GEMM with N=128.
// ---------------------------------------------------------------------------
#define NODE_TILE 64
#define XPAD 68

__global__ void __launch_bounds__(512, 2) node_kernel(
    const float* __restrict__ emb,
    const float* __restrict__ Wi, const float* __restrict__ bi,
    const float* __restrict__ Wj, const float* __restrict__ bj)
{
    __shared__ float Wc[FDIM * 128];
    __shared__ float bc[128];
    __shared__ float xs[NODE_TILE * XPAD];

    const int tid = threadIdx.x;
    for (int i = tid; i < FDIM * FDIM; i += 512) {
        const int k = i >> 6, c = i & 63;
        Wc[k * 128 + c]      = Wi[i];
        Wc[k * 128 + 64 + c] = Wj[i];
    }
    if (tid < 64) { bc[tid] = bi[tid]; bc[64 + tid] = bj[tid]; }
    __syncthreads();

    const int qp = tid & 31;
    const int ag = tid >> 5;
    const u64 bias0 = pack2(bc[qp * 4 + 0], bc[qp * 4 + 1]);
    const u64 bias1 = pack2(bc[qp * 4 + 2], bc[qp * 4 + 3]);

    const int ntiles = (NATOMS + NODE_TILE - 1) / NODE_TILE;
    for (int t = blockIdx.x; t < ntiles; t += gridDim.x) {
        for (int i = tid; i < NODE_TILE * 16; i += 512) {
            const int a = i >> 4, qq = i & 15;
            const int atom = t * NODE_TILE + a;
            if (atom < NATOMS) {
                const float4 e = *reinterpret_cast<const float4*>(
                    emb + (size_t)atom * FDIM + qq * 4);
                float4 x;
                x.x = sp(e.x) - LN2F; x.y = sp(e.y) - LN2F;
                x.z = sp(e.z) - LN2F; x.w = sp(e.w) - LN2F;
                *reinterpret_cast<float4*>(xs + a * XPAD + qq * 4) = x;
            }
        }
        __syncthreads();

        u64 acc[4][2];
        #pragma unroll
        for (int i = 0; i < 4; i++) { acc[i][0] = bias0; acc[i][1] = bias1; }

        #pragma unroll 4
        for (int k0 = 0; k0 < FDIM; k0 += 4) {
            ulonglong2 w[4];
            #pragma unroll
            for (int j = 0; j < 4; j++)
                w[j] = *reinterpret_cast<const ulonglong2*>(
                    Wc + (k0 + j) * 128 + qp * 4);
            #pragma unroll
            for (int i = 0; i < 4; i++) {
                const float4 v = *reinterpret_cast<const float4*>(
                    xs + (ag * 4 + i) * XPAD + k0);
                acc[i][0] = fma2(splat2(v.x), w[0].x, acc[i][0]);
                acc[i][1] = fma2(splat2(v.x), w[0].y, acc[i][1]);
                acc[i][0] = fma2(splat2(v.y), w[1].x, acc[i][0]);
                acc[i][1] = fma2(splat2(v.y), w[1].y, acc[i][1]);
                acc[i][0] = fma2(splat2(v.z), w[2].x, acc[i][0]);
                acc[i][1] = fma2(splat2(v.z), w[2].y, acc[i][1]);
                acc[i][0] = fma2(splat2(v.w), w[3].x, acc[i][0]);
                acc[i][1] = fma2(splat2(v.w), w[3].y, acc[i][1]);
            }
        }

        float* const dstbase = (qp < 16) ? g_acc : g_yj;
        const int col = (qp & 15) * 4;
        #pragma unroll
        for (int i = 0; i < 4; i++) {
            const int atom = t * NODE_TILE + ag * 4 + i;
            if (atom < NATOMS) {
                const float2 p0 = unpack2(acc[i][0]);
                const float2 p1 = unpack2(acc[i][1]);
                const float4 o = make_float4(sp(p0.x), sp(p0.y), sp(p1.x), sp(p1.y));
                *reinterpret_cast<float4*>(dstbase + (size_t)atom * FDIM + col) = o;
            }
        }
        __syncthreads();
    }
}

// ---------------------------------------------------------------------------
// CSR build: zero -> histogram -> 2-level exclusive scan -> scatter
// ---------------------------------------------------------------------------
__global__ void zero_kernel() {
    const int i = blockIdx.x * blockDim.x + threadIdx.x;
    if (i < NATOMS) g_cnt[i] = 0;
}

__global__ void hist_kernel(const int* __restrict__ pidx) {
    const int i = blockIdx.x * blockDim.x + threadIdx.x;   // int4 index
    if (i < NPAIRS / 4) {
        const int4 v = __ldg(reinterpret_cast<const int4*>(pidx) + i);
        atomicAdd(&g_cnt[v.x], 1);
        atomicAdd(&g_cnt[v.y], 1);
        atomicAdd(&g_cnt[v.z], 1);
        atomicAdd(&g_cnt[v.w], 1);
    }
}

__global__ void scan_part_kernel() {   // 98 blocks x 256, 1024 counts/block
    __shared__ int ssum[8];
    const int t = threadIdx.x;
    const int base = blockIdx.x * 1024 + t * 4;
    int s = 0;
    #pragma unroll
    for (int i = 0; i < 4; i++) {
        const int idx = base + i;
        s += (idx < NATOMS) ? g_cnt[idx] : 0;
    }
    #pragma unroll
    for (int d = 16; d; d >>= 1) s += __shfl_down_sync(0xffffffffu, s, d);
    if ((t & 31) == 0) ssum[t >> 5] = s;
    __syncthreads();
    if (t == 0) {
        int v = 0;
        #pragma unroll
        for (int i = 0; i < 8; i++) v += ssum[i];
        g_part[blockIdx.x] = v;
    }
}

__global__ void scan_top_kernel() {    // 1 block x 128: exclusive scan of 98
    __shared__ int wsum[4];
    const int t = threadIdx.x, lane = t & 31, w = t >> 5;
    const int v = (t < 98) ? g_part[t] : 0;
    int x = v;
    #pragma unroll
    for (int d = 1; d < 32; d <<= 1) {
        const int n = __shfl_up_sync(0xffffffffu, x, d);
        if (lane >= d) x += n;
    }
    if (lane == 31) wsum[w] = x;
    __syncthreads();
    int woff = 0;
    for (int i = 0; i < w; i++) woff += wsum[i];
    if (t < 98) g_poff[t] = x + woff - v;
}

__global__ void scan_final_kernel() {  // 98 blocks x 256: per-block scan + base
    __shared__ int wtot[8];
    const int t = threadIdx.x, lane = t & 31, w = t >> 5;
    const int base = blockIdx.x * 1024 + t * 4;
    int c[4];
    #pragma unroll
    for (int i = 0; i < 4; i++) {
        const int idx = base + i;
        c[i] = (idx < NATOMS) ? g_cnt[idx] : 0;
    }
    const int s0 = c[0], s1 = s0 + c[1], s2 = s1 + c[2], s3 = s2 + c[3];
    int x = s3;
    #pragma unroll
    for (int d = 1; d < 32; d <<= 1) {
        const int n = __shfl_up_sync(0xffffffffu, x, d);
        if (lane >= d) x += n;
    }
    if (lane == 31) wtot[w] = x;
    __syncthreads();
    int woff = 0;
    for (int i = 0; i < w; i++) woff += wtot[i];
    const int te = x - s3 + woff + g_poff[blockIdx.x];  // thread-exclusive base
    const int o[4] = {te, te + s0, te + s1, te + s2};
    #pragma unroll
    for (int i = 0; i < 4; i++) {
        const int idx = base + i;
        if (idx < NATOMS) { g_off[idx] = o[i]; g_cur[idx] = o[i]; }
    }
}

__global__ void scatter_kernel(const int* __restrict__ pidx) {
    const int p = blockIdx.x * blockDim.x + threadIdx.x;
    if (p < NPAIRS) {
        const int ii = __ldg(pidx + p);
        const int pos = atomicAdd(&g_cur[ii], 1);
        g_plist[pos] = p;
    }
}

// ---------------------------------------------------------------------------
// Gather kernel: one warp per destination atom. Lane owns features
// (2*lane, 2*lane+1); its 32 G coefficients live in registers (no SMEM, no
// atomics). acc = sum over bucket of y_j[c] * (f @ G^T)[c], then v = x_i'+acc.
// ---------------------------------------------------------------------------
__global__ void __launch_bounds__(256) gather_kernel(
    const int* __restrict__ pidx,
    const float* __restrict__ fij,
    const float* __restrict__ G)
{
    const int lane = threadIdx.x & 31;
    const int wid  = threadIdx.x >> 5;

    // G2[r] = {G[2*lane][r], G[2*lane+1][r]}
    u64 G2[RDIM];
    {
        const float4* g0 = reinterpret_cast<const float4*>(G + (2 * lane) * RDIM);
        const float4* g1 = reinterpret_cast<const float4*>(G + (2 * lane + 1) * RDIM);
        #pragma unroll
        for (int r4 = 0; r4 < 4; r4++) {
            const float4 a = __ldg(g0 + r4);
            const float4 b = __ldg(g1 + r4);
            G2[r4 * 4 + 0] = pack2(a.x, b.x);
            G2[r4 * 4 + 1] = pack2(a.y, b.y);
            G2[r4 * 4 + 2] = pack2(a.z, b.z);
            G2[r4 * 4 + 3] = pack2(a.w, b.w);
        }
    }

    const int atom = blockIdx.x * 8 + wid;
    if (atom >= NATOMS) return;

    const int beg = __ldg(g_off + atom);
    const int n   = __ldg(g_cnt + atom);

    u64 acc = 0ull;
    int p = (n > 0) ? __ldg(g_plist + beg) : 0;
    for (int k = 0; k < n; k++) {
        const int pnext = (k + 1 < n) ? __ldg(g_plist + beg + k + 1) : 0;
        const int jj = __ldg(pidx + NPAIRS + p);
        const float4* frow = reinterpret_cast<const float4*>(fij + (size_t)p * RDIM);
        const float4 f0 = __ldg(frow + 0);
        const float4 f1 = __ldg(frow + 1);
        const float4 f2 = __ldg(frow + 2);
        const float4 f3 = __ldg(frow + 3);

        u64 fa = 0ull, fb = 0ull;    // split chain for ILP
        fa = fma2(splat2(f0.x), G2[0],  fa);
        fb = fma2(splat2(f0.y), G2[1],  fb);
        fa = fma2(splat2(f0.z), G2[2],  fa);
        fb = fma2(splat2(f0.w), G2[3],  fb);
        fa = fma2(splat2(f1.x), G2[4],  fa);
        fb = fma2(splat2(f1.y), G2[5],  fb);
        fa = fma2(splat2(f1.z), G2[6],  fa);
        fb = fma2(splat2(f1.w), G2[7],  fb);
        fa = fma2(splat2(f2.x), G2[8],  fa);
        fb = fma2(splat2(f2.y), G2[9],  fb);
        fa = fma2(splat2(f2.z), G2[10], fa);
        fb = fma2(splat2(f2.w), G2[11], fb);
        fa = fma2(splat2(f3.x), G2[12], fa);
        fb = fma2(splat2(f3.y), G2[13], fb);
        fa = fma2(splat2(f3.z), G2[14], fa);
        fb = fma2(splat2(f3.w), G2[15], fb);
        const u64 fp = add2(fa, fb);

        const float2 y = __ldg(reinterpret_cast<const float2*>(
            g_yj + (size_t)jj * FDIM + 2 * lane));
        acc = fma2(fp, pack2(y.x, y.y), acc);

        p = pnext;
    }

    float* dst = g_acc + (size_t)atom * FDIM + 2 * lane;
    const float2 xi = *reinterpret_cast<const float2*>(dst);
    const float2 s = unpack2(acc);
    *reinterpret_cast<float2*>(dst) = make_float2(xi.x + s.x, xi.y + s.y);
}

// ---------------------------------------------------------------------------
// Kernel 3: epilogue (unchanged from R11).
// ---------------------------------------------------------------------------
#define EPI_TILE 128
#define VPAD 68

__device__ __forceinline__ void gemm_tile(const float* __restrict__ W,
                                          const float* __restrict__ rows,
                                          int ag, int q,
                                          const float* __restrict__ bias,
                                          float4 o[4])
{
    const u64 b0 = pack2(bias[q * 4 + 0], bias[q * 4 + 1]);
    const u64 b1 = pack2(bias[q * 4 + 2], bias[q * 4 + 3]);
    u64 acc[4][2];
    #pragma unroll
    for (int i = 0; i < 4; i++) { acc[i][0] = b0; acc[i][1] = b1; }

    #pragma unroll 4
    for (int k0 = 0; k0 < FDIM; k0 += 4) {
        ulonglong2 w[4];
        #pragma unroll
        for (int j = 0; j < 4; j++)
            w[j] = *reinterpret_cast<const ulonglong2*>(W + (k0 + j) * 64 + q * 4);
        #pragma unroll
        for (int i = 0; i < 4; i++) {
            const float4 v = *reinterpret_cast<const float4*>(
                rows + (ag * 4 + i) * VPAD + k0);
            acc[i][0] = fma2(splat2(v.x), w[0].x, acc[i][0]);
            acc[i][1] = fma2(splat2(v.x), w[0].y, acc[i][1]);
            acc[i][0] = fma2(splat2(v.y), w[1].x, acc[i][0]);
            acc[i][1] = fma2(splat2(v.y), w[1].y, acc[i][1]);
            acc[i][0] = fma2(splat2(v.z), w[2].x, acc[i][0]);
            acc[i][1] = fma2(splat2(v.z), w[2].y, acc[i][1]);
            acc[i][0] = fma2(splat2(v.w), w[3].x, acc[i][0]);
            acc[i][1] = fma2(splat2(v.w), w[3].y, acc[i][1]);
        }
    }
    #pragma unroll
    for (int i = 0; i < 4; i++) {
        const float2 p0 = unpack2(acc[i][0]);
        const float2 p1 = unpack2(acc[i][1]);
        o[i] = make_float4(p0.x, p0.y, p1.x, p1.y);
    }
}

__global__ void __launch_bounds__(512) epi_kernel(
    const float* __restrict__ rW1, const float* __restrict__ rb1,
    const float* __restrict__ rW2, const float* __restrict__ rb2,
    const float* __restrict__ Wv,  const float* __restrict__ bv,
    float* __restrict__ out)
{
    extern __shared__ float sm[];
    float* Wsh = sm;
    float* vs  = Wsh + 7 * 4096;
    float* hs  = vs  + EPI_TILE * VPAD;
    float* b1s = hs  + EPI_TILE * VPAD;
    float* b2s = b1s + 192;
    float* bvs = b2s + 192;

    const int tid = threadIdx.x;
    for (int i = tid; i < 3 * 4096; i += 512) {
        Wsh[i] = rW1[i];
        Wsh[3 * 4096 + i] = rW2[i];
    }
    for (int i = tid; i < 4096; i += 512) Wsh[6 * 4096 + i] = Wv[i];
    if (tid < 192) { b1s[tid] = rb1[tid]; b2s[tid] = rb2[tid]; }
    if (tid < 64) bvs[tid] = bv[tid];
    __syncthreads();

    const int q  = tid & 15;
    const int ag = tid >> 4;

    const int ntiles = (NATOMS + EPI_TILE - 1) / EPI_TILE;
    for (int t = blockIdx.x; t < ntiles; t += gridDim.x) {
        const int abase = t * EPI_TILE + ag * 4;

        float4 v[4];
        #pragma unroll
        for (int i = 0; i < 4; i++) {
            const int atom = abase + i;
            v[i] = (atom < NATOMS)
                 ? *reinterpret_cast<const float4*>(g_acc + (size_t)atom * FDIM + q * 4)
                 : make_float4(0.f, 0.f, 0.f, 0.f);
            *reinterpret_cast<float4*>(vs + (ag * 4 + i) * VPAD + q * 4) = v[i];
        }
        __syncthreads();

        #pragma unroll 1
        for (int l = 0; l < 3; l++) {
            float4 h[4];
            gemm_tile(Wsh + l * 4096, vs, ag, q, b1s + l * 64, h);
            #pragma unroll
            for (int i = 0; i < 4; i++) {
                h[i].x = sp(h[i].x); h[i].y = sp(h[i].y);
                h[i].z = sp(h[i].z); h[i].w = sp(h[i].w);
                *reinterpret_cast<float4*>(hs + (ag * 4 + i) * VPAD + q * 4) = h[i];
            }
            __syncthreads();

            float4 d[4];
            gemm_tile(Wsh + (3 + l) * 4096, hs, ag, q, b2s + l * 64, d);
            #pragma unroll
            for (int i = 0; i < 4; i++) {
                v[i].x += d[i].x; v[i].y += d[i].y;
                v[i].z += d[i].z; v[i].w += d[i].w;
                *reinterpret_cast<float4*>(vs + (ag * 4 + i) * VPAD + q * 4) = v[i];
            }
            __syncthreads();
        }

        #pragma unroll
        for (int i = 0; i < 4; i++) {
            const float4 s = make_float4(sp(v[i].x), sp(v[i].y), sp(v[i].z), sp(v[i].w));
            *reinterpret_cast<float4*>(hs + (ag * 4 + i) * VPAD + q * 4) = s;
        }
        __syncthreads();

        float4 o[4];
        gemm_tile(Wsh + 6 * 4096, hs, ag, q, bvs, o);
        #pragma unroll
        for (int i = 0; i < 4; i++) {
            const int atom = abase + i;
            if (atom < NATOMS)
                *reinterpret_cast<float4*>(out + (size_t)atom * FDIM + q * 4) = o[i];
        }
        __syncthreads();
    }
}

// ---------------------------------------------------------------------------
extern "C" void kernel_launch(void* const* d_in, const int* in_sizes, int n_in,
                              void* d_out, int out_size)
{
    const int*   pidx = (const int*)  d_in[0];
    const float* fij  = (const float*)d_in[1];
    const float* emb  = (const float*)d_in[3];
    const float* G    = (const float*)d_in[4];
    const float* Wi   = (const float*)d_in[5];
    const float* bi   = (const float*)d_in[6];
    const float* Wj   = (const float*)d_in[7];
    const float* bj   = (const float*)d_in[8];
    const float* rW1  = (const float*)d_in[9];
    const float* rb1  = (const float*)d_in[10];
    const float* rW2  = (const float*)d_in[11];
    const float* rb2  = (const float*)d_in[12];
    const float* Wv   = (const float*)d_in[13];
    const float* bv   = (const float*)d_in[14];
    float* out = (float*)d_out;

    // CSR build (independent of node math, stream-ordered)
    zero_kernel<<<(NATOMS + 255) / 256, 256>>>();
    hist_kernel<<<(NPAIRS / 4 + 255) / 256, 256>>>(pidx);
    scan_part_kernel<<<98, 256>>>();
    scan_top_kernel<<<1, 128>>>();
    scan_final_kernel<<<98, 256>>>();
    scatter_kernel<<<(NPAIRS + 255) / 256, 256>>>(pidx);

    // Node transforms (g_acc = x_i', g_yj = x_j')
    node_kernel<<<296, 512>>>(emb, Wi, bi, Wj, bj);

    // Warp-per-atom message aggregation (no atomics, no SMEM in hot loop)
    gather_kernel<<<(NATOMS + 7) / 8, 256>>>(pidx, fij, G);

    // Residual MLP chain + output projection
    const int epi_smem = (7 * 4096 + 2 * EPI_TILE * VPAD + 192 + 192 + 64) * 4;
    cudaFuncSetAttribute(epi_kernel, cudaFuncAttributeMaxDynamicSharedMemorySize,
                         epi_smem);
    epi_kernel<<<148, 512, epi_smem>>>(rW1, rb1, rW2, rb2, Wv, bv, out);
}

// round 16
// speedup vs baseline: 1.4284x; 1.4284x over previous
#include <cuda_runtime.h>

#define NATOMS 100000
#define NPAIRS 2000000
#define FDIM 64
#define RDIM 16
#define LN2F 0.6931471805599453f

typedef unsigned long long u64;

// Scratch (device globals: allocation-free per harness rules)
__device__ float g_yj[NATOMS * FDIM];   // softplus(x@Wj+bj) per atom
__device__ float g_acc[NATOMS * FDIM];  // x_i' accumulator; pairs red into it

__device__ __forceinline__ float sp(float x) {
    return fmaxf(x, 0.f) + log1pf(__expf(-fabsf(x)));
}

// ---- packed f32x2 helpers ----
__device__ __forceinline__ u64 fma2(u64 a, u64 b, u64 c) {
    u64 d;
    asm("fma.rn.f32x2 %0, %1, %2, %3;" : "=l"(d) : "l"(a), "l"(b), "l"(c));
    return d;
}
__device__ __forceinline__ u64 add2(u64 a, u64 b) {
    u64 d;
    asm("add.rn.f32x2 %0, %1, %2;" : "=l"(d) : "l"(a), "l"(b));
    return d;
}
__device__ __forceinline__ u64 mul2(u64 a, u64 b) {
    u64 d;
    asm("mul.rn.f32x2 %0, %1, %2;" : "=l"(d) : "l"(a), "l"(b));
    return d;
}
__device__ __forceinline__ u64 splat2(float v) {
    u64 r;
    asm("mov.b64 %0, {%1, %1};" : "=l"(r) : "f"(v));
    return r;
}
__device__ __forceinline__ u64 pack2(float lo, float hi) {
    u64 r;
    asm("mov.b64 %0, {%1, %2};" : "=l"(r) : "f"(lo), "f"(hi));
    return r;
}
__device__ __forceinline__ float2 unpack2(u64 v) {
    float lo, hi;
    asm("mov.b64 {%0, %1}, %2;" : "=f"(lo), "=f"(hi) : "l"(v));
    return make_float2(lo, hi);
}

// ---------------------------------------------------------------------------
// Kernel 1: node transforms. x = sp(emb)-ln2; g_acc = sp(x@Wi+bi);
// g_yj = sp(x@Wj+bj). One GEMM with N=128 (Wi|Wj concatenated).
// ---------------------------------------------------------------------------
#define NODE_TILE 64
#define XPAD 68

__global__ void __launch_bounds__(512, 2) node_kernel(
    const float* __restrict__ emb,
    const float* __restrict__ Wi, const float* __restrict__ bi,
    const float* __restrict__ Wj, const float* __restrict__ bj)
{
    __shared__ float Wc[FDIM * 128];
    __shared__ float bc[128];
    __shared__ float xs[NODE_TILE * XPAD];

    const int tid = threadIdx.x;
    for (int i = tid; i < FDIM * FDIM; i += 512) {
        const int k = i >> 6, c = i & 63;
        Wc[k * 128 + c]      = Wi[i];
        Wc[k * 128 + 64 + c] = Wj[i];
    }
    if (tid < 64) { bc[tid] = bi[tid]; bc[64 + tid] = bj[tid]; }
    __syncthreads();

    const int qp = tid & 31;
    const int ag = tid >> 5;
    const u64 bias0 = pack2(bc[qp * 4 + 0], bc[qp * 4 + 1]);
    const u64 bias1 = pack2(bc[qp * 4 + 2], bc[qp * 4 + 3]);

    const int ntiles = (NATOMS + NODE_TILE - 1) / NODE_TILE;
    for (int t = blockIdx.x; t < ntiles; t += gridDim.x) {
        for (int i = tid; i < NODE_TILE * 16; i += 512) {
            const int a = i >> 4, qq = i & 15;
            const int atom = t * NODE_TILE + a;
            if (atom < NATOMS) {
                const float4 e = *reinterpret_cast<const float4*>(
                    emb + (size_t)atom * FDIM + qq * 4);
                float4 x;
                x.x = sp(e.x) - LN2F; x.y = sp(e.y) - LN2F;
                x.z = sp(e.z) - LN2F; x.w = sp(e.w) - LN2F;
                *reinterpret_cast<float4*>(xs + a * XPAD + qq * 4) = x;
            }
        }
        __syncthreads();

        u64 acc[4][2];
        #pragma unroll
        for (int i = 0; i < 4; i++) { acc[i][0] = bias0; acc[i][1] = bias1; }

        #pragma unroll 4
        for (int k0 = 0; k0 < FDIM; k0 += 4) {
            ulonglong2 w[4];
            #pragma unroll
            for (int j = 0; j < 4; j++)
                w[j] = *reinterpret_cast<const ulonglong2*>(
                    Wc + (k0 + j) * 128 + qp * 4);
            #pragma unroll
            for (int i = 0; i < 4; i++) {
                const float4 v = *reinterpret_cast<const float4*>(
                    xs + (ag * 4 + i) * XPAD + k0);
                acc[i][0] = fma2(splat2(v.x), w[0].x, acc[i][0]);
                acc[i][1] = fma2(splat2(v.x), w[0].y, acc[i][1]);
                acc[i][0] = fma2(splat2(v.y), w[1].x, acc[i][0]);
                acc[i][1] = fma2(splat2(v.y), w[1].y, acc[i][1]);
                acc[i][0] = fma2(splat2(v.z), w[2].x, acc[i][0]);
                acc[i][1] = fma2(splat2(v.z), w[2].y, acc[i][1]);
                acc[i][0] = fma2(splat2(v.w), w[3].x, acc[i][0]);
                acc[i][1] = fma2(splat2(v.w), w[3].y, acc[i][1]);
            }
        }

        float* const dstbase = (qp < 16) ? g_acc : g_yj;
        const int col = (qp & 15) * 4;
        #pragma unroll
        for (int i = 0; i < 4; i++) {
            const int atom = t * NODE_TILE + ag * 4 + i;
            if (atom < NATOMS) {
                const float2 p0 = unpack2(acc[i][0]);
                const float2 p1 = unpack2(acc[i][1]);
                const float4 o = make_float4(sp(p0.x), sp(p0.y), sp(p1.x), sp(p1.y));
                *reinterpret_cast<float4*>(dstbase + (size_t)atom * FDIM + col) = o;
            }
        }
        __syncthreads();
    }
}

// ---------------------------------------------------------------------------
// Kernel 2: warp-per-pair, G entirely in registers (2 features per lane,
// 16 u64 coefficients). Zero shared-memory traffic in the hot loop.
// Per pair: f-row loads are warp-uniform, y_j gather is one coalesced 256B
// row, scatter is red.global.add.v2.f32 (one coalesced 256B atomic row).
// Two pairs per iteration so all loads issue before the red barriers.
// ---------------------------------------------------------------------------
__device__ __forceinline__ u64 fprime2(const float4& f0, const float4& f1,
                                       const float4& f2, const float4& f3,
                                       const u64* __restrict__ G2)
{
    u64 fa = 0ull, fb = 0ull;
    fa = fma2(splat2(f0.x), G2[0],  fa);
    fb = fma2(splat2(f0.y), G2[1],  fb);
    fa = fma2(splat2(f0.z), G2[2],  fa);
    fb = fma2(splat2(f0.w), G2[3],  fb);
    fa = fma2(splat2(f1.x), G2[4],  fa);
    fb = fma2(splat2(f1.y), G2[5],  fb);
    fa = fma2(splat2(f1.z), G2[6],  fa);
    fb = fma2(splat2(f1.w), G2[7],  fb);
    fa = fma2(splat2(f2.x), G2[8],  fa);
    fb = fma2(splat2(f2.y), G2[9],  fb);
    fa = fma2(splat2(f2.z), G2[10], fa);
    fb = fma2(splat2(f2.w), G2[11], fb);
    fa = fma2(splat2(f3.x), G2[12], fa);
    fb = fma2(splat2(f3.y), G2[13], fb);
    fa = fma2(splat2(f3.z), G2[14], fa);
    fb = fma2(splat2(f3.w), G2[15], fb);
    return add2(fa, fb);
}

__global__ void __launch_bounds__(256) pair_kernel(
    const int* __restrict__ pidx,
    const float* __restrict__ fij,
    const float* __restrict__ G)
{
    const int lane = threadIdx.x & 31;

    // G2[r] = {G[2*lane][r], G[2*lane+1][r]}  — the 2 output features this
    // lane owns, for all 16 radial basis inputs. Lives in registers.
    u64 G2[RDIM];
    {
        const float4* g0 = reinterpret_cast<const float4*>(G + (2 * lane) * RDIM);
        const float4* g1 = reinterpret_cast<const float4*>(G + (2 * lane + 1) * RDIM);
        #pragma unroll
        for (int r4 = 0; r4 < 4; r4++) {
            const float4 a = __ldg(g0 + r4);
            const float4 b = __ldg(g1 + r4);
            G2[r4 * 4 + 0] = pack2(a.x, b.x);
            G2[r4 * 4 + 1] = pack2(a.y, b.y);
            G2[r4 * 4 + 2] = pack2(a.z, b.z);
            G2[r4 * 4 + 3] = pack2(a.w, b.w);
        }
    }

    const int warp   = blockIdx.x * (blockDim.x >> 5) + (threadIdx.x >> 5);
    const int nwarps = gridDim.x * (blockDim.x >> 5);

    // NPAIRS is even and p0 is even, so p0 < NPAIRS implies p0+1 < NPAIRS.
    for (int p0 = warp * 2; p0 < NPAIRS; p0 += nwarps * 2) {
        const int p1 = p0 + 1;

        // --- issue ALL loads for both pairs up front (pipelined) ---
        const int ii0 = __ldg(pidx + p0);
        const int jj0 = __ldg(pidx + NPAIRS + p0);
        const int ii1 = __ldg(pidx + p1);
        const int jj1 = __ldg(pidx + NPAIRS + p1);

        const float4* fr0 = reinterpret_cast<const float4*>(fij + (size_t)p0 * RDIM);
        const float4* fr1 = reinterpret_cast<const float4*>(fij + (size_t)p1 * RDIM);
        const float4 a0 = __ldg(fr0 + 0), a1 = __ldg(fr0 + 1);
        const float4 a2 = __ldg(fr0 + 2), a3 = __ldg(fr0 + 3);
        const float4 b0 = __ldg(fr1 + 0), b1 = __ldg(fr1 + 1);
        const float4 b2 = __ldg(fr1 + 2), b3 = __ldg(fr1 + 3);

        const float2 y0 = __ldg(reinterpret_cast<const float2*>(
            g_yj + (size_t)jj0 * FDIM + 2 * lane));
        const float2 y1 = __ldg(reinterpret_cast<const float2*>(
            g_yj + (size_t)jj1 * FDIM + 2 * lane));

        // --- compute both messages ---
        const u64 fp0 = fprime2(a0, a1, a2, a3, G2);
        const u64 fp1 = fprime2(b0, b1, b2, b3, G2);
        const float2 m0 = unpack2(mul2(fp0, pack2(y0.x, y0.y)));
        const float2 m1 = unpack2(mul2(fp1, pack2(y1.x, y1.y)));

        // --- coalesced vector reductions (256B row per pair per warp) ---
        float* d0 = g_acc + (size_t)ii0 * FDIM + 2 * lane;
        asm volatile("red.global.add.v2.f32 [%0], {%1,%2};"
                     :: "l"(d0), "f"(m0.x), "f"(m0.y) : "memory");
        float* d1 = g_acc + (size_t)ii1 * FDIM + 2 * lane;
        asm volatile("red.global.add.v2.f32 [%0], {%1,%2};"
                     :: "l"(d1), "f"(m1.x), "f"(m1.y) : "memory");
    }
}

// ---------------------------------------------------------------------------
// Kernel 3: epilogue. 7 chained 64x64 matmuls per atom, 4-atom register
// blocking + f32x2. 512 threads = 32 atom-groups x 16 col-groups.
// ---------------------------------------------------------------------------
#define EPI_TILE 128
#define VPAD 68

__device__ __forceinline__ void gemm_tile(const float* __restrict__ W,
                                          const float* __restrict__ rows,
                                          int ag, int q,
                                          const float* __restrict__ bias,
                                          float4 o[4])
{
    const u64 b0 = pack2(bias[q * 4 + 0], bias[q * 4 + 1]);
    const u64 b1 = pack2(bias[q * 4 + 2], bias[q * 4 + 3]);
    u64 acc[4][2];
    #pragma unroll
    for (int i = 0; i < 4; i++) { acc[i][0] = b0; acc[i][1] = b1; }

    #pragma unroll 4
    for (int k0 = 0; k0 < FDIM; k0 += 4) {
        ulonglong2 w[4];
        #pragma unroll
        for (int j = 0; j < 4; j++)
            w[j] = *reinterpret_cast<const ulonglong2*>(W + (k0 + j) * 64 + q * 4);
        #pragma unroll
        for (int i = 0; i < 4; i++) {
            const float4 v = *reinterpret_cast<const float4*>(
                rows + (ag * 4 + i) * VPAD + k0);
            acc[i][0] = fma2(splat2(v.x), w[0].x, acc[i][0]);
            acc[i][1] = fma2(splat2(v.x), w[0].y, acc[i][1]);
            acc[i][0] = fma2(splat2(v.y), w[1].x, acc[i][0]);
            acc[i][1] = fma2(splat2(v.y), w[1].y, acc[i][1]);
            acc[i][0] = fma2(splat2(v.z), w[2].x, acc[i][0]);
            acc[i][1] = fma2(splat2(v.z), w[2].y, acc[i][1]);
            acc[i][0] = fma2(splat2(v.w), w[3].x, acc[i][0]);
            acc[i][1] = fma2(splat2(v.w), w[3].y, acc[i][1]);
        }
    }
    #pragma unroll
    for (int i = 0; i < 4; i++) {
        const float2 p0 = unpack2(acc[i][0]);
        const float2 p1 = unpack2(acc[i][1]);
        o[i] = make_float4(p0.x, p0.y, p1.x, p1.y);
    }
}

__global__ void __launch_bounds__(512) epi_kernel(
    const float* __restrict__ rW1, const float* __restrict__ rb1,
    const float* __restrict__ rW2, const float* __restrict__ rb2,
    const float* __restrict__ Wv,  const float* __restrict__ bv,
    float* __restrict__ out)
{
    extern __shared__ float sm[];
    float* Wsh = sm;
    float* vs  = Wsh + 7 * 4096;
    float* hs  = vs  + EPI_TILE * VPAD;
    float* b1s = hs  + EPI_TILE * VPAD;
    float* b2s = b1s + 192;
    float* bvs = b2s + 192;

    const int tid = threadIdx.x;
    for (int i = tid; i < 3 * 4096; i += 512) {
        Wsh[i] = rW1[i];
        Wsh[3 * 4096 + i] = rW2[i];
    }
    for (int i = tid; i < 4096; i += 512) Wsh[6 * 4096 + i] = Wv[i];
    if (tid < 192) { b1s[tid] = rb1[tid]; b2s[tid] = rb2[tid]; }
    if (tid < 64) bvs[tid] = bv[tid];
    __syncthreads();

    const int q  = tid & 15;
    const int ag = tid >> 4;

    const int ntiles = (NATOMS + EPI_TILE - 1) / EPI_TILE;
    for (int t = blockIdx.x; t < ntiles; t += gridDim.x) {
        const int abase = t * EPI_TILE + ag * 4;

        float4 v[4];
        #pragma unroll
        for (int i = 0; i < 4; i++) {
            const int atom = abase + i;
            v[i] = (atom < NATOMS)
                 ? *reinterpret_cast<const float4*>(g_acc + (size_t)atom * FDIM + q * 4)
                 : make_float4(0.f, 0.f, 0.f, 0.f);
            *reinterpret_cast<float4*>(vs + (ag * 4 + i) * VPAD + q * 4) = v[i];
        }
        __syncthreads();

        #pragma unroll 1
        for (int l = 0; l < 3; l++) {
            float4 h[4];
            gemm_tile(Wsh + l * 4096, vs, ag, q, b1s + l * 64, h);
            #pragma unroll
            for (int i = 0; i < 4; i++) {
                h[i].x = sp(h[i].x); h[i].y = sp(h[i].y);
                h[i].z = sp(h[i].z); h[i].w = sp(h[i].w);
                *reinterpret_cast<float4*>(hs + (ag * 4 + i) * VPAD + q * 4) = h[i];
            }
            __syncthreads();

            float4 d[4];
            gemm_tile(Wsh + (3 + l) * 4096, hs, ag, q, b2s + l * 64, d);
            #pragma unroll
            for (int i = 0; i < 4; i++) {
                v[i].x += d[i].x; v[i].y += d[i].y;
                v[i].z += d[i].z; v[i].w += d[i].w;
                *reinterpret_cast<float4*>(vs + (ag * 4 + i) * VPAD + q * 4) = v[i];
            }
            __syncthreads();
        }

        #pragma unroll
        for (int i = 0; i < 4; i++) {
            const float4 s = make_float4(sp(v[i].x), sp(v[i].y), sp(v[i].z), sp(v[i].w));
            *reinterpret_cast<float4*>(hs + (ag * 4 + i) * VPAD + q * 4) = s;
        }
        __syncthreads();

        float4 o[4];
        gemm_tile(Wsh + 6 * 4096, hs, ag, q, bvs, o);
        #pragma unroll
        for (int i = 0; i < 4; i++) {
            const int atom = abase + i;
            if (atom < NATOMS)
                *reinterpret_cast<float4*>(out + (size_t)atom * FDIM + q * 4) = o[i];
        }
        __syncthreads();
    }
}

// ---------------------------------------------------------------------------
extern "C" void kernel_launch(void* const* d_in, const int* in_sizes, int n_in,
                              void* d_out, int out_size)
{
    const int*   pidx = (const int*)  d_in[0];
    const float* fij  = (const float*)d_in[1];
    const float* emb  = (const float*)d_in[3];
    const float* G    = (const float*)d_in[4];
    const float* Wi   = (const float*)d_in[5];
    const float* bi   = (const float*)d_in[6];
    const float* Wj   = (const float*)d_in[7];
    const float* bj   = (const float*)d_in[8];
    const float* rW1  = (const float*)d_in[9];
    const float* rb1  = (const float*)d_in[10];
    const float* rW2  = (const float*)d_in[11];
    const float* rb2  = (const float*)d_in[12];
    const float* Wv   = (const float*)d_in[13];
    const float* bv   = (const float*)d_in[14];
    float* out = (float*)d_out;

    // Kernel 1: node transforms (g_acc = x_i', g_yj = x_j')
    node_kernel<<<296, 512>>>(emb, Wi, bi, Wj, bj);

    // Kernel 2: warp-per-pair messages, G in registers, no SMEM, red.v2 scatter
    pair_kernel<<<592, 256>>>(pidx, fij, G);

    // Kernel 3: residual MLP chain + output projection
    const int epi_smem = (7 * 4096 + 2 * EPI_TILE * VPAD + 192 + 192 + 64) * 4;
    cudaFuncSetAttribute(epi_kernel, cudaFuncAttributeMaxDynamicSharedMemorySize,
                         epi_smem);
    epi_kernel<<<148, 512, epi_smem>>>(rW1, rb1, rW2, rb2, Wv, bv, out);
}